// round 2
// baseline (speedup 1.0000x reference)
#include <cuda_runtime.h>
#include <math.h>
#include <float.h>

#define NN    50000
#define EE    800000
#define ELNUM 850000          // EE + NN self loops
#define FIN   16
#define HIDD  64
#define NHEAD 4
#define CC    64
#define HC    256             // NHEAD*CC
#define GG    64
#define NEG   0.2f

// ---------------- scratch (device globals; no allocation) ----------------
__device__ int   g_is64;               // 1 if edge_index/batch are int64
__device__ int   g_src[ELNUM];
__device__ int   g_dst[ELNUM];
__device__ int   g_batch[NN];
__device__ float g_h [NN * HIDD];      // node features between layers
__device__ float g_hw[NN * HC];        // h @ W^T  [N, H, C]
__device__ float g_as[NN * NHEAD];     // alpha_src per node
__device__ float g_ad[NN * NHEAD];     // alpha_dst per node
__device__ float g_e [(size_t)ELNUM * NHEAD];  // per-edge logits/exp/alpha, layout [h*EL + e]
__device__ float g_m [NN * NHEAD];     // segment max
__device__ float g_s [NN * NHEAD];     // segment sum
__device__ float g_o [NN * HC];        // aggregated messages
__device__ float g_pool[GG * HIDD];
__device__ float g_cnt [GG];

__device__ __forceinline__ void atomicMaxF(float* addr, float val) {
    int* a = (int*)addr;
    int old = *a;
    while (__int_as_float(old) < val) {
        int assumed = old;
        old = atomicCAS(a, assumed, __float_as_int(val));
        if (old == assumed) break;
    }
}

// ---------------- dtype probe + index conversion ----------------
__global__ void k_detect(const void* ei) {
    // int64 little-endian values < 2^31  =>  all odd int32 words are zero.
    const int* p = (const int*)ei;
    int all0 = 1;
    for (int k = 1; k < 128; k += 2)
        if (p[k] != 0) { all0 = 0; break; }
    g_is64 = all0;
}

__global__ void k_convert(const void* ei, const void* batch) {
    int i = blockIdx.x * blockDim.x + threadIdx.x;
    int is64 = g_is64;
    if (i < ELNUM) {
        int s, d;
        if (i < EE) {
            if (is64) {
                s = (int)((const long long*)ei)[i];
                d = (int)((const long long*)ei)[EE + i];
            } else {
                s = ((const int*)ei)[i];
                d = ((const int*)ei)[EE + i];
            }
        } else {
            s = d = i - EE;   // self loop
        }
        g_src[i] = s; g_dst[i] = d;
    }
    if (i < NN) {
        g_batch[i] = is64 ? (int)((const long long*)batch)[i]
                          : ((const int*)batch)[i];
    }
}

// ---------------- kernels ----------------
__global__ void k_lin_in(const float* __restrict__ x, const float* __restrict__ W,
                         const float* __restrict__ b) {
    int i = blockIdx.x * blockDim.x + threadIdx.x;
    if (i >= NN * HIDD) return;
    int n = i / HIDD, c = i % HIDD;
    const float* xr = x + n * FIN;
    const float* wr = W + c * FIN;
    float s = b[c];
#pragma unroll
    for (int k = 0; k < FIN; k++) s += xr[k] * wr[k];
    g_h[i] = s;
}

__global__ void k_init_layer() {
    int i = blockIdx.x * blockDim.x + threadIdx.x;
    if (i < NN * HC) g_o[i] = 0.f;
    if (i < NN * NHEAD) { g_m[i] = -FLT_MAX; g_s[i] = 0.f; }
}

__global__ void k_hw(const float* __restrict__ W) {
    int i = blockIdx.x * blockDim.x + threadIdx.x;
    if (i >= NN * HC) return;
    int n = i / HC, c = i % HC;
    const float* hr = g_h + n * HIDD;
    const float* wr = W + c * HIDD;
    float s = 0.f;
#pragma unroll
    for (int k = 0; k < HIDD; k++) s += hr[k] * wr[k];
    g_hw[i] = s;
}

__global__ void k_alpha(const float* __restrict__ asrc, const float* __restrict__ adst) {
    int i = blockIdx.x * blockDim.x + threadIdx.x;
    if (i >= NN * NHEAD) return;
    int n = i / NHEAD, h = i % NHEAD;
    const float* hr = g_hw + n * HC + h * CC;
    const float* a1 = asrc + h * CC;
    const float* a2 = adst + h * CC;
    float s1 = 0.f, s2 = 0.f;
#pragma unroll
    for (int k = 0; k < CC; k++) { float v = hr[k]; s1 += v * a1[k]; s2 += v * a2[k]; }
    g_as[i] = s1; g_ad[i] = s2;
}

__global__ void k_edge_max() {
    int i = blockIdx.x * blockDim.x + threadIdx.x;
    if (i >= ELNUM * NHEAD) return;
    int e = i % ELNUM, h = i / ELNUM;
    int s = g_src[e], d = g_dst[e];
    float v = g_as[s * NHEAD + h] + g_ad[d * NHEAD + h];
    v = (v < 0.f) ? v * NEG : v;      // leaky relu
    g_e[i] = v;
    atomicMaxF(&g_m[d * NHEAD + h], v);
}

__global__ void k_edge_exp() {
    int i = blockIdx.x * blockDim.x + threadIdx.x;
    if (i >= ELNUM * NHEAD) return;
    int e = i % ELNUM, h = i / ELNUM;
    int d = g_dst[e];
    float v = expf(g_e[i] - g_m[d * NHEAD + h]);
    g_e[i] = v;
    atomicAdd(&g_s[d * NHEAD + h], v);
}

__global__ void k_edge_norm() {
    int i = blockIdx.x * blockDim.x + threadIdx.x;
    if (i >= ELNUM * NHEAD) return;
    int e = i % ELNUM, h = i / ELNUM;
    int d = g_dst[e];
    g_e[i] = g_e[i] / (g_s[d * NHEAD + h] + 1e-16f);
}

__global__ void k_scatter() {
    int i = blockIdx.x * blockDim.x + threadIdx.x;
    if (i >= ELNUM * CC) return;
    int e = i / CC, c = i % CC;
    int s = g_src[e], d = g_dst[e];
#pragma unroll
    for (int h = 0; h < NHEAD; h++) {
        float a = g_e[(size_t)h * ELNUM + e];
        atomicAdd(&g_o[d * HC + h * CC + c], a * g_hw[s * HC + h * CC + c]);
    }
}

__global__ void k_head_mean(const float* __restrict__ bg) {
    int i = blockIdx.x * blockDim.x + threadIdx.x;
    if (i >= NN * HIDD) return;
    int n = i / HIDD, c = i % HIDD;
    float s = 0.f;
#pragma unroll
    for (int h = 0; h < NHEAD; h++) s += g_o[n * HC + h * CC + c];
    s = s * (1.f / NHEAD) + bg[c];
    g_h[i] = (s > 0.f) ? s : 0.f;     // relu
}

__global__ void k_pool_init() {
    int i = blockIdx.x * blockDim.x + threadIdx.x;
    if (i < GG * HIDD) g_pool[i] = 0.f;
    if (i < GG) g_cnt[i] = 0.f;
}

__global__ void k_pool() {
    int i = blockIdx.x * blockDim.x + threadIdx.x;
    if (i >= NN * HIDD) return;
    int n = i / HIDD, c = i % HIDD;
    int g = g_batch[n];
    atomicAdd(&g_pool[g * HIDD + c], g_h[i]);
    if (c == 0) atomicAdd(&g_cnt[g], 1.f);
}

__global__ void k_final(const float* __restrict__ Wout, const float* __restrict__ bout,
                        float* __restrict__ out) {
    int g = threadIdx.x;
    if (g >= GG) return;
    float cnt = fmaxf(g_cnt[g], 1.f);
    float s = 0.f;
#pragma unroll
    for (int c = 0; c < HIDD; c++) s += (g_pool[g * HIDD + c] / cnt) * Wout[c];
    out[g] = 1.f / (1.f + expf(-(s + bout[0])));
}

// ---------------- launch ----------------
extern "C" void kernel_launch(void* const* d_in, const int* in_sizes, int n_in,
                              void* d_out, int out_size) {
    // Input index maps: setup_inputs dict order vs reference signature order.
    int ix, iei, ib, iwin, ibin, iwout, ibout, iw[3], ias[3], iad[3], ibg[3];
    if (n_in >= 2 && in_sizes[1] == 2 * EE) {
        // dict order: x, edge_index, batch, W_in, b_in, W_out, b_out, (W,asrc,adst,bg)x3
        ix = 0; iei = 1; ib = 2; iwin = 3; ibin = 4; iwout = 5; ibout = 6;
        for (int l = 0; l < 3; l++) { iw[l] = 7 + 4 * l; ias[l] = 8 + 4 * l; iad[l] = 9 + 4 * l; ibg[l] = 10 + 4 * l; }
    } else {
        // signature order: x, W_in, b_in, (W,asrc,adst,bg)x3, W_out, b_out, edge_index, batch
        ix = 0; iwin = 1; ibin = 2;
        for (int l = 0; l < 3; l++) { iw[l] = 3 + 4 * l; ias[l] = 4 + 4 * l; iad[l] = 5 + 4 * l; ibg[l] = 6 + 4 * l; }
        iwout = 15; ibout = 16; iei = 17; ib = 18;
    }

    const float* x     = (const float*)d_in[ix];
    const void*  ei    = d_in[iei];
    const void*  batch = d_in[ib];
    const float* W_in  = (const float*)d_in[iwin];
    const float* b_in  = (const float*)d_in[ibin];
    const float* W_out = (const float*)d_in[iwout];
    const float* b_out = (const float*)d_in[ibout];
    float* out = (float*)d_out;

    const int T = 256;
    auto gsz = [](long long n, int t) { return (int)((n + t - 1) / t); };

    k_detect<<<1, 1>>>(ei);
    k_convert<<<gsz(ELNUM, T), T>>>(ei, batch);
    k_lin_in<<<gsz((long long)NN * HIDD, T), T>>>(x, W_in, b_in);

    for (int l = 0; l < 3; l++) {
        const float* W  = (const float*)d_in[iw[l]];
        const float* as = (const float*)d_in[ias[l]];
        const float* ad = (const float*)d_in[iad[l]];
        const float* bg = (const float*)d_in[ibg[l]];

        k_init_layer<<<gsz((long long)NN * HC, T), T>>>();
        k_hw<<<gsz((long long)NN * HC, T), T>>>(W);
        k_alpha<<<gsz((long long)NN * NHEAD, T), T>>>(as, ad);
        k_edge_max<<<gsz((long long)ELNUM * NHEAD, T), T>>>();
        k_edge_exp<<<gsz((long long)ELNUM * NHEAD, T), T>>>();
        k_edge_norm<<<gsz((long long)ELNUM * NHEAD, T), T>>>();
        k_scatter<<<gsz((long long)ELNUM * CC, T), T>>>();
        k_head_mean<<<gsz((long long)NN * HIDD, T), T>>>(bg);
    }

    k_pool_init<<<gsz((long long)GG * HIDD, T), T>>>();
    k_pool<<<gsz((long long)NN * HIDD, T), T>>>();
    k_final<<<1, 64>>>(W_out, b_out, out);
}

// round 3
// speedup vs baseline: 10.0163x; 10.0163x over previous
#include <cuda_runtime.h>
#include <math.h>
#include <float.h>

#define NN    50000
#define EE    800000
#define ELNUM 850000          // EE + NN self loops
#define FIN   16
#define HIDD  64
#define NHEAD 4
#define CC    64
#define HC    256             // NHEAD*CC
#define GG    64
#define NEG   0.2f

// ---------------- scratch (device globals; no allocation) ----------------
__device__ int   g_is64;
__device__ int   g_src[ELNUM];
__device__ int   g_dst[ELNUM];
__device__ int   g_batch[NN];
__device__ int   g_deg[NN];
__device__ int   g_cursor[NN];
__device__ int   g_rowptr[NN + 1];
__device__ int   g_csr_src[ELNUM];
__device__ float g_h [NN * HIDD];             // node features between layers
__device__ float g_hw[NN * HC];               // h @ W^T  [N, 256]
__device__ float g_wt[HIDD * HC];             // W^T [64, 256]
__device__ float g_as[NN * NHEAD];            // a_src . h  per node
__device__ float g_ad[NN * NHEAD];            // a_dst . h  per node
__device__ float g_e [(size_t)ELNUM * NHEAD]; // per-edge alpha, CSR order [pos*4+h]
__device__ float g_pool[GG * HIDD];
__device__ float g_cnt [GG];

// ---------------- dtype probe + index conversion + degree count ----------------
__global__ void k_detect(const void* ei) {
    const int* p = (const int*)ei;
    int all0 = 1;
    for (int k = 1; k < 128; k += 2)
        if (p[k] != 0) { all0 = 0; break; }
    g_is64 = all0;
}

__global__ void k_zero_build() {
    int i = blockIdx.x * blockDim.x + threadIdx.x;
    if (i < NN) { g_deg[i] = 0; g_cursor[i] = 0; }
}

__global__ void k_convert(const void* ei, const void* batch) {
    int i = blockIdx.x * blockDim.x + threadIdx.x;
    int is64 = g_is64;
    if (i < ELNUM) {
        int s, d;
        if (i < EE) {
            if (is64) {
                s = (int)((const long long*)ei)[i];
                d = (int)((const long long*)ei)[EE + i];
            } else {
                s = ((const int*)ei)[i];
                d = ((const int*)ei)[EE + i];
            }
        } else {
            s = d = i - EE;   // self loop
        }
        g_src[i] = s; g_dst[i] = d;
        atomicAdd(&g_deg[d], 1);
    }
    if (i < NN) {
        g_batch[i] = is64 ? (int)((const long long*)batch)[i]
                          : ((const int*)batch)[i];
    }
}

// single-block exclusive scan of g_deg -> g_rowptr
__global__ void k_scan() {
    __shared__ int sdata[1024];
    __shared__ int carry;
    int tid = threadIdx.x;
    if (tid == 0) { carry = 0; g_rowptr[0] = 0; }
    __syncthreads();
    for (int base = 0; base < NN; base += 1024) {
        int v = (base + tid < NN) ? g_deg[base + tid] : 0;
        sdata[tid] = v;
        __syncthreads();
        for (int off = 1; off < 1024; off <<= 1) {
            int t = (tid >= off) ? sdata[tid - off] : 0;
            __syncthreads();
            sdata[tid] += t;
            __syncthreads();
        }
        if (base + tid < NN) g_rowptr[base + tid + 1] = carry + sdata[tid];
        __syncthreads();
        if (tid == 0) carry += sdata[1023];
        __syncthreads();
    }
}

__global__ void k_fill() {
    int i = blockIdx.x * blockDim.x + threadIdx.x;
    if (i >= ELNUM) return;
    int d = g_dst[i];
    int pos = g_rowptr[d] + atomicAdd(&g_cursor[d], 1);
    g_csr_src[pos] = g_src[i];
}

// ---------------- compute kernels ----------------
__global__ void k_lin_in(const float* __restrict__ x, const float* __restrict__ W,
                         const float* __restrict__ b) {
    int i = blockIdx.x * blockDim.x + threadIdx.x;
    if (i >= NN * HIDD) return;
    int n = i / HIDD, c = i % HIDD;
    const float* xr = x + n * FIN;
    const float* wr = W + c * FIN;
    float s = b[c];
#pragma unroll
    for (int k = 0; k < FIN; k++) s += xr[k] * wr[k];
    g_h[i] = s;
}

__global__ void k_transpose(const float* __restrict__ W) {
    int i = blockIdx.x * blockDim.x + threadIdx.x;   // i = k*256 + c
    if (i >= HIDD * HC) return;
    int k = i / HC, c = i % HC;
    g_wt[i] = W[c * HIDD + k];
}

// block = 1 node, 256 threads.  hw row + fused alpha dots.
__global__ void k_hw_alpha(const float* __restrict__ asrc, const float* __restrict__ adst) {
    __shared__ float sh_h[HIDD];
    __shared__ float sh_s[HC];
    int n = blockIdx.x;
    int t = threadIdx.x;
    if (t < HIDD) sh_h[t] = g_h[n * HIDD + t];
    __syncthreads();
    float s = 0.f;
#pragma unroll
    for (int k = 0; k < HIDD; k++) s += sh_h[k] * g_wt[k * HC + t];
    g_hw[n * HC + t] = s;
    sh_s[t] = s;
    __syncthreads();
    if (t < 32) {
        // lane covers channels c = t + 32j ; head = j>>1 ; asrc/adst flat index = c
        float p1[NHEAD] = {0.f, 0.f, 0.f, 0.f};
        float p2[NHEAD] = {0.f, 0.f, 0.f, 0.f};
#pragma unroll
        for (int j = 0; j < 8; j++) {
            int c = 32 * j + t;
            float v = sh_s[c];
            p1[j >> 1] += v * asrc[c];
            p2[j >> 1] += v * adst[c];
        }
#pragma unroll
        for (int h = 0; h < NHEAD; h++) {
#pragma unroll
            for (int off = 16; off > 0; off >>= 1) {
                p1[h] += __shfl_down_sync(0xffffffffu, p1[h], off);
                p2[h] += __shfl_down_sync(0xffffffffu, p2[h], off);
            }
        }
        if (t == 0) {
#pragma unroll
            for (int h = 0; h < NHEAD; h++) {
                g_as[n * NHEAD + h] = p1[h];
                g_ad[n * NHEAD + h] = p2[h];
            }
        }
    }
}

// thread per (node, head): register-resident segment softmax over CSR row
__global__ void k_softmax() {
    int i = blockIdx.x * blockDim.x + threadIdx.x;
    if (i >= NN * NHEAD) return;
    int n = i >> 2, h = i & 3;
    int r0 = g_rowptr[n], r1 = g_rowptr[n + 1];
    float ad = g_ad[n * NHEAD + h];
    float m = -FLT_MAX;
    for (int p = r0; p < r1; p++) {
        float v = g_as[g_csr_src[p] * NHEAD + h] + ad;
        v = (v < 0.f) ? v * NEG : v;
        g_e[(size_t)p * NHEAD + h] = v;
        m = fmaxf(m, v);
    }
    float sum = 0.f;
    for (int p = r0; p < r1; p++) {
        float v = expf(g_e[(size_t)p * NHEAD + h] - m);
        g_e[(size_t)p * NHEAD + h] = v;
        sum += v;
    }
    float inv = 1.f / (sum + 1e-16f);
    for (int p = r0; p < r1; p++)
        g_e[(size_t)p * NHEAD + h] *= inv;
}

// warp per node: gather-reduce messages, fused head-mean + bias + relu
__global__ void k_gather(const float* __restrict__ bg) {
    int wid = (blockIdx.x * blockDim.x + threadIdx.x) >> 5;
    int lane = threadIdx.x & 31;
    if (wid >= NN) return;
    int n = wid;
    int r0 = g_rowptr[n], r1 = g_rowptr[n + 1];
    float acc[8] = {0.f, 0.f, 0.f, 0.f, 0.f, 0.f, 0.f, 0.f};
    for (int p = r0; p < r1; p++) {
        int src = g_csr_src[p];                               // broadcast
        float4 a = *(const float4*)(g_e + (size_t)p * NHEAD); // broadcast
        const float* hw = g_hw + (size_t)src * HC + lane;
        const float* av = &a.x;
#pragma unroll
        for (int j = 0; j < 8; j++)
            acc[j] += av[j >> 1] * hw[j * 32];
    }
    // c = 32j + lane ; head = j>>1 ; within-head channel = 32*(j&1) + lane
#pragma unroll
    for (int q = 0; q < 2; q++) {
        float v = (acc[q] + acc[q + 2] + acc[q + 4] + acc[q + 6]) * 0.25f
                + bg[q * 32 + lane];
        g_h[n * HIDD + q * 32 + lane] = (v > 0.f) ? v : 0.f;
    }
}

__global__ void k_pool_init() {
    int i = blockIdx.x * blockDim.x + threadIdx.x;
    if (i < GG * HIDD) g_pool[i] = 0.f;
    if (i < GG) g_cnt[i] = 0.f;
}

__global__ void k_pool() {
    int i = blockIdx.x * blockDim.x + threadIdx.x;
    if (i >= NN * HIDD) return;
    int n = i / HIDD, c = i % HIDD;
    int g = g_batch[n];
    atomicAdd(&g_pool[g * HIDD + c], g_h[i]);
    if (c == 0) atomicAdd(&g_cnt[g], 1.f);
}

__global__ void k_final(const float* __restrict__ Wout, const float* __restrict__ bout,
                        float* __restrict__ out) {
    int g = threadIdx.x;
    if (g >= GG) return;
    float cnt = fmaxf(g_cnt[g], 1.f);
    float s = 0.f;
#pragma unroll
    for (int c = 0; c < HIDD; c++) s += (g_pool[g * HIDD + c] / cnt) * Wout[c];
    out[g] = 1.f / (1.f + expf(-(s + bout[0])));
}

// ---------------- launch ----------------
extern "C" void kernel_launch(void* const* d_in, const int* in_sizes, int n_in,
                              void* d_out, int out_size) {
    int ix, iei, ib, iwin, ibin, iwout, ibout, iw[3], ias[3], iad[3], ibg[3];
    if (n_in >= 2 && in_sizes[1] == 2 * EE) {
        ix = 0; iei = 1; ib = 2; iwin = 3; ibin = 4; iwout = 5; ibout = 6;
        for (int l = 0; l < 3; l++) { iw[l] = 7 + 4 * l; ias[l] = 8 + 4 * l; iad[l] = 9 + 4 * l; ibg[l] = 10 + 4 * l; }
    } else {
        ix = 0; iwin = 1; ibin = 2;
        for (int l = 0; l < 3; l++) { iw[l] = 3 + 4 * l; ias[l] = 4 + 4 * l; iad[l] = 5 + 4 * l; ibg[l] = 6 + 4 * l; }
        iwout = 15; ibout = 16; iei = 17; ib = 18;
    }

    const float* x     = (const float*)d_in[ix];
    const void*  ei    = d_in[iei];
    const void*  batch = d_in[ib];
    const float* W_in  = (const float*)d_in[iwin];
    const float* b_in  = (const float*)d_in[ibin];
    const float* W_out = (const float*)d_in[iwout];
    const float* b_out = (const float*)d_in[ibout];
    float* out = (float*)d_out;

    const int T = 256;
    auto gsz = [](long long n, int t) { return (int)((n + t - 1) / t); };

    // graph preprocessing (once per launch)
    k_detect<<<1, 1>>>(ei);
    k_zero_build<<<gsz(NN, T), T>>>();
    k_convert<<<gsz(ELNUM, T), T>>>(ei, batch);
    k_scan<<<1, 1024>>>();
    k_fill<<<gsz(ELNUM, T), T>>>();

    k_lin_in<<<gsz((long long)NN * HIDD, T), T>>>(x, W_in, b_in);

    for (int l = 0; l < 3; l++) {
        const float* W  = (const float*)d_in[iw[l]];
        const float* as = (const float*)d_in[ias[l]];
        const float* ad = (const float*)d_in[iad[l]];
        const float* bg = (const float*)d_in[ibg[l]];

        k_transpose<<<gsz(HIDD * HC, T), T>>>(W);
        k_hw_alpha<<<NN, HC>>>(as, ad);
        k_softmax<<<gsz((long long)NN * NHEAD, T), T>>>();
        k_gather<<<gsz((long long)NN * 32, T), T>>>(bg);
    }

    k_pool_init<<<gsz((long long)GG * HIDD, T), T>>>();
    k_pool<<<gsz((long long)NN * HIDD, T), T>>>();
    k_final<<<1, 64>>>(W_out, b_out, out);
}

// round 4
// speedup vs baseline: 15.0389x; 1.5014x over previous
#include <cuda_runtime.h>
#include <math.h>
#include <float.h>

#define NN    50000
#define EE    800000
#define ELNUM 850000          // EE + NN self loops
#define FIN   16
#define HIDD  64
#define NHEAD 4
#define CC    64
#define HC    256             // NHEAD*CC
#define GG    64
#define NEG   0.2f

#define SCAN_B    1024
#define SCAN_NBLK ((NN + SCAN_B - 1) / SCAN_B)   // 49

// ---------------- scratch (device globals; no allocation) ----------------
__device__ int   g_is64;
__device__ int   g_src[ELNUM];
__device__ int   g_dst[ELNUM];
__device__ int   g_batch[NN];
__device__ int   g_deg[NN];
__device__ int   g_cursor[NN];
__device__ int   g_rowptr[NN + 1];
__device__ int   g_bsum[SCAN_NBLK];
__device__ int   g_boff[SCAN_NBLK];
__device__ int   g_csr_src[ELNUM];
__device__ __align__(16) float g_h [NN * HIDD];             // node features between layers
__device__ __align__(16) float g_hw[(size_t)NN * HC];       // h @ W^T  [N, 256]
__device__ __align__(16) float g_wt[HIDD * HC];             // W^T [64, 256]
__device__ __align__(16) float g_as[NN * NHEAD];            // a_src . h  per node
__device__ __align__(16) float g_ad[NN * NHEAD];            // a_dst . h  per node
__device__ __align__(16) float g_inv[NN * NHEAD];           // 1/(sum_exp + eps)
__device__ __align__(16) float g_e [(size_t)ELNUM * NHEAD]; // per-edge exp, CSR order [p*4+h]
__device__ float g_pool[GG * HIDD];
__device__ float g_cnt [GG];

// ---------------- dtype probe + index conversion + degree count ----------------
__global__ void k_detect(const void* ei) {
    const int* p = (const int*)ei;
    int all0 = 1;
    for (int k = 1; k < 128; k += 2)
        if (p[k] != 0) { all0 = 0; break; }
    g_is64 = all0;
}

__global__ void k_zero_build() {
    int i = blockIdx.x * blockDim.x + threadIdx.x;
    if (i < NN) { g_deg[i] = 0; g_cursor[i] = 0; }
}

__global__ void k_convert(const void* ei, const void* batch) {
    int i = blockIdx.x * blockDim.x + threadIdx.x;
    int is64 = g_is64;
    if (i < ELNUM) {
        int s, d;
        if (i < EE) {
            if (is64) {
                s = (int)((const long long*)ei)[i];
                d = (int)((const long long*)ei)[EE + i];
            } else {
                s = ((const int*)ei)[i];
                d = ((const int*)ei)[EE + i];
            }
        } else {
            s = d = i - EE;   // self loop
        }
        g_src[i] = s; g_dst[i] = d;
        atomicAdd(&g_deg[d], 1);
    }
    if (i < NN) {
        g_batch[i] = is64 ? (int)((const long long*)batch)[i]
                          : ((const int*)batch)[i];
    }
}

// ---------------- parallel exclusive scan: deg -> rowptr ----------------
__global__ void k_scan1() {
    __shared__ int ws[32];
    int b = blockIdx.x, tid = threadIdx.x;
    int i = b * SCAN_B + tid;
    int lane = tid & 31, w = tid >> 5;
    int x = (i < NN) ? g_deg[i] : 0;
#pragma unroll
    for (int o = 1; o < 32; o <<= 1) {
        int y = __shfl_up_sync(0xffffffffu, x, o);
        if (lane >= o) x += y;
    }
    if (lane == 31) ws[w] = x;
    __syncthreads();
    if (w == 0) {
        int y = ws[lane];
#pragma unroll
        for (int o = 1; o < 32; o <<= 1) {
            int z = __shfl_up_sync(0xffffffffu, y, o);
            if (lane >= o) y += z;
        }
        ws[lane] = y;
    }
    __syncthreads();
    int incl = x + (w > 0 ? ws[w - 1] : 0);
    if (i < NN) g_rowptr[i + 1] = incl;
    if (tid == SCAN_B - 1) g_bsum[b] = incl;
}

__global__ void k_scan2() {
    if (threadIdx.x == 0) {
        int run = 0;
        for (int b = 0; b < SCAN_NBLK; b++) { g_boff[b] = run; run += g_bsum[b]; }
        g_rowptr[0] = 0;
    }
}

__global__ void k_scan3() {
    int i = blockIdx.x * blockDim.x + threadIdx.x;
    if (i >= NN) return;
    int b = i >> 10;
    if (b > 0) g_rowptr[i + 1] += g_boff[b];
}

__global__ void k_fill() {
    int i = blockIdx.x * blockDim.x + threadIdx.x;
    if (i >= ELNUM) return;
    int d = g_dst[i];
    int pos = g_rowptr[d] + atomicAdd(&g_cursor[d], 1);
    g_csr_src[pos] = g_src[i];
}

// ---------------- compute kernels ----------------
__global__ void k_lin_in(const float* __restrict__ x, const float* __restrict__ W,
                         const float* __restrict__ b) {
    int i = blockIdx.x * blockDim.x + threadIdx.x;
    if (i >= NN * HIDD) return;
    int n = i / HIDD, c = i % HIDD;
    const float* xr = x + n * FIN;
    const float* wr = W + c * FIN;
    float s = b[c];
#pragma unroll
    for (int k = 0; k < FIN; k++) s += xr[k] * wr[k];
    g_h[i] = s;
}

__global__ void k_transpose(const float* __restrict__ W) {
    int i = blockIdx.x * blockDim.x + threadIdx.x;   // i = k*256 + c
    if (i >= HIDD * HC) return;
    int k = i / HC, c = i % HC;
    g_wt[i] = W[c * HIDD + k];
}

// block = 4 nodes, 256 threads. hw rows + fused alpha dots (all 8 warps).
#define MB 4
__global__ void k_hw_alpha(const float* __restrict__ asrc, const float* __restrict__ adst) {
    __shared__ float sh_h[MB][HIDD];
    __shared__ float sh_s[MB][HC];
    int n0 = blockIdx.x * MB;
    int t = threadIdx.x;
    {
        int nb = t >> 6, c = t & 63;
        sh_h[nb][c] = g_h[(n0 + nb) * HIDD + c];
    }
    __syncthreads();
    float acc[MB] = {0.f, 0.f, 0.f, 0.f};
#pragma unroll
    for (int k = 0; k < HIDD; k++) {
        float w = g_wt[k * HC + t];
#pragma unroll
        for (int m = 0; m < MB; m++) acc[m] += sh_h[m][k] * w;
    }
#pragma unroll
    for (int m = 0; m < MB; m++) {
        g_hw[(size_t)(n0 + m) * HC + t] = acc[m];
        sh_s[m][t] = acc[m];
    }
    __syncthreads();
    // warp wI: node nb = wI>>1, which = wI&1 (0=src, 1=dst)
    int wI = t >> 5, lane = t & 31;
    int nb = wI >> 1;
    const float* a = (wI & 1) ? adst : asrc;
    float p[NHEAD] = {0.f, 0.f, 0.f, 0.f};
#pragma unroll
    for (int j = 0; j < 8; j++) {
        int c = 32 * j + lane;
        p[j >> 1] += sh_s[nb][c] * a[c];
    }
#pragma unroll
    for (int h = 0; h < NHEAD; h++)
#pragma unroll
        for (int off = 16; off > 0; off >>= 1)
            p[h] += __shfl_down_sync(0xffffffffu, p[h], off);
    if (lane == 0) {
        float* dstp = (wI & 1) ? g_ad : g_as;
#pragma unroll
        for (int h = 0; h < NHEAD; h++) dstp[(n0 + nb) * NHEAD + h] = p[h];
    }
}

// warp per node: segment softmax; stores exp in g_e (CSR float4) and 1/sum in g_inv
__global__ void k_softmax() {
    int wid = (blockIdx.x * blockDim.x + threadIdx.x) >> 5;
    int lane = threadIdx.x & 31;
    if (wid >= NN) return;
    int n = wid;
    int r0 = g_rowptr[n], r1 = g_rowptr[n + 1];
    float4 adv = *(const float4*)(g_ad + n * NHEAD);
    float4* e4 = (float4*)g_e;
    float mx[NHEAD] = {-FLT_MAX, -FLT_MAX, -FLT_MAX, -FLT_MAX};
    for (int p = r0 + lane; p < r1; p += 32) {
        int src = g_csr_src[p];
        float4 as4 = *(const float4*)(g_as + src * NHEAD);
        float v0 = as4.x + adv.x; v0 = (v0 < 0.f) ? v0 * NEG : v0;
        float v1 = as4.y + adv.y; v1 = (v1 < 0.f) ? v1 * NEG : v1;
        float v2 = as4.z + adv.z; v2 = (v2 < 0.f) ? v2 * NEG : v2;
        float v3 = as4.w + adv.w; v3 = (v3 < 0.f) ? v3 * NEG : v3;
        e4[p] = make_float4(v0, v1, v2, v3);
        mx[0] = fmaxf(mx[0], v0); mx[1] = fmaxf(mx[1], v1);
        mx[2] = fmaxf(mx[2], v2); mx[3] = fmaxf(mx[3], v3);
    }
#pragma unroll
    for (int h = 0; h < NHEAD; h++)
#pragma unroll
        for (int off = 16; off > 0; off >>= 1)
            mx[h] = fmaxf(mx[h], __shfl_xor_sync(0xffffffffu, mx[h], off));
    float sm[NHEAD] = {0.f, 0.f, 0.f, 0.f};
    for (int p = r0 + lane; p < r1; p += 32) {
        float4 v = e4[p];
        v.x = __expf(v.x - mx[0]); v.y = __expf(v.y - mx[1]);
        v.z = __expf(v.z - mx[2]); v.w = __expf(v.w - mx[3]);
        e4[p] = v;
        sm[0] += v.x; sm[1] += v.y; sm[2] += v.z; sm[3] += v.w;
    }
#pragma unroll
    for (int h = 0; h < NHEAD; h++)
#pragma unroll
        for (int off = 16; off > 0; off >>= 1)
            sm[h] += __shfl_xor_sync(0xffffffffu, sm[h], off);
    if (lane == 0) {
        float4 inv;
        inv.x = 1.f / (sm[0] + 1e-16f); inv.y = 1.f / (sm[1] + 1e-16f);
        inv.z = 1.f / (sm[2] + 1e-16f); inv.w = 1.f / (sm[3] + 1e-16f);
        *(float4*)(g_inv + n * NHEAD) = inv;
    }
}

// warp per node: gather-reduce (float4 loads), inv+head-mean+bias+relu epilogue
__global__ void k_gather(const float* __restrict__ bg) {
    int wid = (blockIdx.x * blockDim.x + threadIdx.x) >> 5;
    int lane = threadIdx.x & 31;
    if (wid >= NN) return;
    int n = wid;
    int r0 = g_rowptr[n], r1 = g_rowptr[n + 1];
    const float4* e4 = (const float4*)g_e;
    int hsel = lane >> 4;          // 0 or 1
    float acc0[4] = {0.f, 0.f, 0.f, 0.f};   // channels lane*4+q      (head hsel)
    float acc1[4] = {0.f, 0.f, 0.f, 0.f};   // channels 128+lane*4+q  (head 2+hsel)
    int p = r0;
    for (; p + 1 < r1; p += 2) {
        int s0 = g_csr_src[p], s1 = g_csr_src[p + 1];
        float4 a0 = e4[p], a1 = e4[p + 1];
        const float4* h0 = (const float4*)(g_hw + (size_t)s0 * HC);
        const float4* h1 = (const float4*)(g_hw + (size_t)s1 * HC);
        float4 x0 = h0[lane], y0 = h0[32 + lane];
        float4 x1 = h1[lane], y1 = h1[32 + lane];
        float ea0 = hsel ? a0.y : a0.x, eb0 = hsel ? a0.w : a0.z;
        float ea1 = hsel ? a1.y : a1.x, eb1 = hsel ? a1.w : a1.z;
        acc0[0] += ea0 * x0.x; acc0[1] += ea0 * x0.y; acc0[2] += ea0 * x0.z; acc0[3] += ea0 * x0.w;
        acc1[0] += eb0 * y0.x; acc1[1] += eb0 * y0.y; acc1[2] += eb0 * y0.z; acc1[3] += eb0 * y0.w;
        acc0[0] += ea1 * x1.x; acc0[1] += ea1 * x1.y; acc0[2] += ea1 * x1.z; acc0[3] += ea1 * x1.w;
        acc1[0] += eb1 * y1.x; acc1[1] += eb1 * y1.y; acc1[2] += eb1 * y1.z; acc1[3] += eb1 * y1.w;
    }
    if (p < r1) {
        int s0 = g_csr_src[p];
        float4 a0 = e4[p];
        const float4* h0 = (const float4*)(g_hw + (size_t)s0 * HC);
        float4 x0 = h0[lane], y0 = h0[32 + lane];
        float ea0 = hsel ? a0.y : a0.x, eb0 = hsel ? a0.w : a0.z;
        acc0[0] += ea0 * x0.x; acc0[1] += ea0 * x0.y; acc0[2] += ea0 * x0.z; acc0[3] += ea0 * x0.w;
        acc1[0] += eb0 * y0.x; acc1[1] += eb0 * y0.y; acc1[2] += eb0 * y0.z; acc1[3] += eb0 * y0.w;
    }
    float4 inv = *(const float4*)(g_inv + n * NHEAD);
    float ia = hsel ? inv.y : inv.x;
    float ib = hsel ? inv.w : inv.z;
    float out4[4];
#pragma unroll
    for (int q = 0; q < 4; q++) {
        float s = acc0[q] * ia + acc1[q] * ib;
        s += __shfl_xor_sync(0xffffffffu, s, 16);
        out4[q] = s;
    }
    if (lane < 16) {
#pragma unroll
        for (int q = 0; q < 4; q++) {
            float v = out4[q] * 0.25f + bg[lane * 4 + q];
            out4[q] = (v > 0.f) ? v : 0.f;
        }
        *(float4*)(g_h + (size_t)n * HIDD + lane * 4) = *(float4*)out4;
    }
}

__global__ void k_pool_init() {
    int i = blockIdx.x * blockDim.x + threadIdx.x;
    if (i < GG * HIDD) g_pool[i] = 0.f;
    if (i < GG) g_cnt[i] = 0.f;
}

__global__ void k_pool() {
    int i = blockIdx.x * blockDim.x + threadIdx.x;
    if (i >= NN * HIDD) return;
    int n = i / HIDD, c = i % HIDD;
    int g = g_batch[n];
    atomicAdd(&g_pool[g * HIDD + c], g_h[i]);
    if (c == 0) atomicAdd(&g_cnt[g], 1.f);
}

__global__ void k_final(const float* __restrict__ Wout, const float* __restrict__ bout,
                        float* __restrict__ out) {
    int g = threadIdx.x;
    if (g >= GG) return;
    float cnt = fmaxf(g_cnt[g], 1.f);
    float s = 0.f;
#pragma unroll
    for (int c = 0; c < HIDD; c++) s += (g_pool[g * HIDD + c] / cnt) * Wout[c];
    out[g] = 1.f / (1.f + expf(-(s + bout[0])));
}

// ---------------- launch ----------------
extern "C" void kernel_launch(void* const* d_in, const int* in_sizes, int n_in,
                              void* d_out, int out_size) {
    int ix, iei, ib, iwin, ibin, iwout, ibout, iw[3], ias[3], iad[3], ibg[3];
    if (n_in >= 2 && in_sizes[1] == 2 * EE) {
        ix = 0; iei = 1; ib = 2; iwin = 3; ibin = 4; iwout = 5; ibout = 6;
        for (int l = 0; l < 3; l++) { iw[l] = 7 + 4 * l; ias[l] = 8 + 4 * l; iad[l] = 9 + 4 * l; ibg[l] = 10 + 4 * l; }
    } else {
        ix = 0; iwin = 1; ibin = 2;
        for (int l = 0; l < 3; l++) { iw[l] = 3 + 4 * l; ias[l] = 4 + 4 * l; iad[l] = 5 + 4 * l; ibg[l] = 6 + 4 * l; }
        iwout = 15; ibout = 16; iei = 17; ib = 18;
    }

    const float* x     = (const float*)d_in[ix];
    const void*  ei    = d_in[iei];
    const void*  batch = d_in[ib];
    const float* W_in  = (const float*)d_in[iwin];
    const float* b_in  = (const float*)d_in[ibin];
    const float* W_out = (const float*)d_in[iwout];
    const float* b_out = (const float*)d_in[ibout];
    float* out = (float*)d_out;

    const int T = 256;
    auto gsz = [](long long n, int t) { return (int)((n + t - 1) / t); };

    // graph preprocessing (once per launch)
    k_detect<<<1, 1>>>(ei);
    k_zero_build<<<gsz(NN, T), T>>>();
    k_convert<<<gsz(ELNUM, T), T>>>(ei, batch);
    k_scan1<<<SCAN_NBLK, SCAN_B>>>();
    k_scan2<<<1, 32>>>();
    k_scan3<<<gsz(NN, T), T>>>();
    k_fill<<<gsz(ELNUM, T), T>>>();

    k_lin_in<<<gsz((long long)NN * HIDD, T), T>>>(x, W_in, b_in);

    for (int l = 0; l < 3; l++) {
        const float* W  = (const float*)d_in[iw[l]];
        const float* as = (const float*)d_in[ias[l]];
        const float* ad = (const float*)d_in[iad[l]];
        const float* bg = (const float*)d_in[ibg[l]];

        k_transpose<<<gsz(HIDD * HC, T), T>>>(W);
        k_hw_alpha<<<NN / MB, HC>>>(as, ad);
        k_softmax<<<gsz((long long)NN * 32, T), T>>>();
        k_gather<<<gsz((long long)NN * 32, T), T>>>(bg);
    }

    k_pool_init<<<gsz((long long)GG * HIDD, T), T>>>();
    k_pool<<<gsz((long long)NN * HIDD, T), T>>>();
    k_final<<<1, 64>>>(W_out, b_out, out);
}

// round 5
// speedup vs baseline: 15.8657x; 1.0550x over previous
#include <cuda_runtime.h>
#include <cuda_fp16.h>
#include <math.h>
#include <float.h>

#define NN    50000
#define EE    800000
#define ELNUM 850000          // EE + NN self loops
#define FIN   16
#define HIDD  64
#define NHEAD 4
#define CC    64
#define HC    256             // NHEAD*CC
#define GG    64
#define NEG   0.2f

#define SCAN_B    1024
#define SCAN_NBLK ((NN + SCAN_B - 1) / SCAN_B)   // 49

typedef unsigned long long ull;

// ---------------- scratch (device globals; no allocation) ----------------
__device__ int   g_is64;
__device__ int   g_src[ELNUM];
__device__ int   g_dst[ELNUM];
__device__ int   g_batch[NN];
__device__ int   g_deg[NN];
__device__ int   g_cursor[NN];
__device__ int   g_rowptr[NN + 1];
__device__ int   g_bsum[SCAN_NBLK];
__device__ int   g_boff[SCAN_NBLK];
__device__ int   g_csr_src[ELNUM];
__device__ __align__(16) float  g_h  [NN * HIDD];       // node features between layers
__device__ __align__(16) __half g_hwh[(size_t)NN * HC]; // h @ W^T as fp16  [N, 256]
__device__ __align__(16) float  g_wt [HIDD * HC];       // W^T [64, 256]
__device__ __align__(16) float  g_as [NN * NHEAD];      // a_src . h  per node
__device__ __align__(16) float  g_ad [NN * NHEAD];      // a_dst . h  per node
__device__ float g_pool[GG * HIDD];
__device__ float g_cnt [GG];

// ---------------- dtype probe + index conversion + degree count ----------------
__global__ void k_detect(const void* ei) {
    const int* p = (const int*)ei;
    int all0 = 1;
    for (int k = 1; k < 128; k += 2)
        if (p[k] != 0) { all0 = 0; break; }
    g_is64 = all0;
}

__global__ void k_zero_build() {
    int i = blockIdx.x * blockDim.x + threadIdx.x;
    if (i < NN) { g_deg[i] = 0; g_cursor[i] = 0; }
}

__global__ void k_convert(const void* ei, const void* batch) {
    int i = blockIdx.x * blockDim.x + threadIdx.x;
    int is64 = g_is64;
    if (i < ELNUM) {
        int s, d;
        if (i < EE) {
            if (is64) {
                s = (int)((const long long*)ei)[i];
                d = (int)((const long long*)ei)[EE + i];
            } else {
                s = ((const int*)ei)[i];
                d = ((const int*)ei)[EE + i];
            }
        } else {
            s = d = i - EE;   // self loop
        }
        g_src[i] = s; g_dst[i] = d;
        atomicAdd(&g_deg[d], 1);
    }
    if (i < NN) {
        g_batch[i] = is64 ? (int)((const long long*)batch)[i]
                          : ((const int*)batch)[i];
    }
}

// ---------------- parallel exclusive scan: deg -> rowptr ----------------
__global__ void k_scan1() {
    __shared__ int ws[32];
    int b = blockIdx.x, tid = threadIdx.x;
    int i = b * SCAN_B + tid;
    int lane = tid & 31, w = tid >> 5;
    int x = (i < NN) ? g_deg[i] : 0;
#pragma unroll
    for (int o = 1; o < 32; o <<= 1) {
        int y = __shfl_up_sync(0xffffffffu, x, o);
        if (lane >= o) x += y;
    }
    if (lane == 31) ws[w] = x;
    __syncthreads();
    if (w == 0) {
        int y = ws[lane];
#pragma unroll
        for (int o = 1; o < 32; o <<= 1) {
            int z = __shfl_up_sync(0xffffffffu, y, o);
            if (lane >= o) y += z;
        }
        ws[lane] = y;
    }
    __syncthreads();
    int incl = x + (w > 0 ? ws[w - 1] : 0);
    if (i < NN) g_rowptr[i + 1] = incl;
    if (tid == SCAN_B - 1) g_bsum[b] = incl;
}

__global__ void k_scan2() {
    if (threadIdx.x == 0) {
        int run = 0;
        for (int b = 0; b < SCAN_NBLK; b++) { g_boff[b] = run; run += g_bsum[b]; }
        g_rowptr[0] = 0;
    }
}

__global__ void k_scan3() {
    int i = blockIdx.x * blockDim.x + threadIdx.x;
    if (i >= NN) return;
    int b = i >> 10;
    if (b > 0) g_rowptr[i + 1] += g_boff[b];
}

__global__ void k_fill() {
    int i = blockIdx.x * blockDim.x + threadIdx.x;
    if (i >= ELNUM) return;
    int d = g_dst[i];
    int pos = g_rowptr[d] + atomicAdd(&g_cursor[d], 1);
    g_csr_src[pos] = g_src[i];
}

// ---------------- compute kernels ----------------
__global__ void k_lin_in(const float* __restrict__ x, const float* __restrict__ W,
                         const float* __restrict__ b) {
    int i = blockIdx.x * blockDim.x + threadIdx.x;
    if (i >= NN * HIDD) return;
    int n = i / HIDD, c = i % HIDD;
    const float* xr = x + n * FIN;
    const float* wr = W + c * FIN;
    float s = b[c];
#pragma unroll
    for (int k = 0; k < FIN; k++) s += xr[k] * wr[k];
    g_h[i] = s;
}

__global__ void k_transpose(const float* __restrict__ W) {
    int i = blockIdx.x * blockDim.x + threadIdx.x;   // i = k*256 + c
    if (i >= HIDD * HC) return;
    int k = i / HC, c = i % HC;
    g_wt[i] = W[c * HIDD + k];
}

// block = 8 nodes, 256 threads. hw rows (FFMA2) + fp16 store + fused alpha dots.
#define MB 8
__global__ void k_hw_alpha(const float* __restrict__ asrc, const float* __restrict__ adst) {
    __shared__ __align__(16) ull sh_h2[HIDD][MB / 2];  // [k][node-pair], packed f32x2
    __shared__ float sh_s[MB][HC];
    int n0 = blockIdx.x * MB;
    int t = threadIdx.x;
    // load h: 8 nodes x 64 feats; ((float*)sh_h2)[k*MB + m]
    for (int idx = t; idx < MB * HIDD; idx += 256) {
        int m = idx >> 6, k = idx & 63;
        ((float*)sh_h2)[k * MB + m] = g_h[(n0 + m) * HIDD + k];
    }
    __syncthreads();
    ull acc2[4] = {0ull, 0ull, 0ull, 0ull};   // bit pattern 0 == (0.f, 0.f)
#pragma unroll 8
    for (int k = 0; k < HIDD; k++) {
        float w = g_wt[k * HC + t];
        ull ww;
        asm("mov.b64 %0, {%1,%1};" : "=l"(ww) : "f"(w));
        ulonglong2 ha = *(const ulonglong2*)&sh_h2[k][0];
        ulonglong2 hb = *(const ulonglong2*)&sh_h2[k][2];
        asm("fma.rn.f32x2 %0, %1, %2, %3;" : "=l"(acc2[0]) : "l"(ha.x), "l"(ww), "l"(acc2[0]));
        asm("fma.rn.f32x2 %0, %1, %2, %3;" : "=l"(acc2[1]) : "l"(ha.y), "l"(ww), "l"(acc2[1]));
        asm("fma.rn.f32x2 %0, %1, %2, %3;" : "=l"(acc2[2]) : "l"(hb.x), "l"(ww), "l"(acc2[2]));
        asm("fma.rn.f32x2 %0, %1, %2, %3;" : "=l"(acc2[3]) : "l"(hb.y), "l"(ww), "l"(acc2[3]));
    }
#pragma unroll
    for (int j = 0; j < 4; j++) {
        float lo, hi;
        asm("mov.b64 {%0, %1}, %2;" : "=f"(lo), "=f"(hi) : "l"(acc2[j]));
        sh_s[2 * j][t] = lo;
        sh_s[2 * j + 1][t] = hi;
        g_hwh[(size_t)(n0 + 2 * j) * HC + t]     = __float2half(lo);
        g_hwh[(size_t)(n0 + 2 * j + 1) * HC + t] = __float2half(hi);
    }
    __syncthreads();
    // warp wI handles node n0+wI: both src and dst dots (4 heads each)
    int wI = t >> 5, lane = t & 31;
    float p[NHEAD] = {0.f, 0.f, 0.f, 0.f};
    float q[NHEAD] = {0.f, 0.f, 0.f, 0.f};
#pragma unroll
    for (int j = 0; j < 8; j++) {
        int c = 32 * j + lane;
        float v = sh_s[wI][c];
        p[j >> 1] += v * asrc[c];
        q[j >> 1] += v * adst[c];
    }
#pragma unroll
    for (int h = 0; h < NHEAD; h++)
#pragma unroll
        for (int off = 16; off > 0; off >>= 1) {
            p[h] += __shfl_xor_sync(0xffffffffu, p[h], off);
            q[h] += __shfl_xor_sync(0xffffffffu, q[h], off);
        }
    if (lane == 0) {
        int n = n0 + wI;
        *(float4*)(g_as + n * NHEAD) = make_float4(p[0], p[1], p[2], p[3]);
        *(float4*)(g_ad + n * NHEAD) = make_float4(q[0], q[1], q[2], q[3]);
    }
}

// warp per node: fused segment softmax + gather-reduce over fp16 messages.
// channel c = lane*8+q ; head = lane>>3 ; within-head channel = (lane&7)*8+q
__global__ void k_attn_gather(const float* __restrict__ bg) {
    int wid = (blockIdx.x * blockDim.x + threadIdx.x) >> 5;
    int lane = threadIdx.x & 31;
    if (wid >= NN) return;
    int n = wid;
    int r0 = g_rowptr[n], r1 = g_rowptr[n + 1];
    float4 adv = *(const float4*)(g_ad + n * NHEAD);

    // pass 1: per-head max over incoming edges
    float m0 = -FLT_MAX, m1 = -FLT_MAX, m2 = -FLT_MAX, m3 = -FLT_MAX;
    for (int p = r0 + lane; p < r1; p += 32) {
        int s = g_csr_src[p];
        float4 a = *(const float4*)(g_as + s * NHEAD);
        float v0 = a.x + adv.x; v0 = (v0 < 0.f) ? v0 * NEG : v0;
        float v1 = a.y + adv.y; v1 = (v1 < 0.f) ? v1 * NEG : v1;
        float v2 = a.z + adv.z; v2 = (v2 < 0.f) ? v2 * NEG : v2;
        float v3 = a.w + adv.w; v3 = (v3 < 0.f) ? v3 * NEG : v3;
        m0 = fmaxf(m0, v0); m1 = fmaxf(m1, v1);
        m2 = fmaxf(m2, v2); m3 = fmaxf(m3, v3);
    }
#pragma unroll
    for (int off = 16; off > 0; off >>= 1) {
        m0 = fmaxf(m0, __shfl_xor_sync(0xffffffffu, m0, off));
        m1 = fmaxf(m1, __shfl_xor_sync(0xffffffffu, m1, off));
        m2 = fmaxf(m2, __shfl_xor_sync(0xffffffffu, m2, off));
        m3 = fmaxf(m3, __shfl_xor_sync(0xffffffffu, m3, off));
    }

    // pass 2: recompute weights, accumulate unnormalized messages
    float acc[8] = {0.f, 0.f, 0.f, 0.f, 0.f, 0.f, 0.f, 0.f};
    float ws0 = 0.f, ws1 = 0.f, ws2 = 0.f, ws3 = 0.f;
    int hsel = lane >> 3;

#define EDGE_STEP(P)                                                          \
    {                                                                         \
        int s_ = g_csr_src[P];                                                \
        float4 a_ = *(const float4*)(g_as + s_ * NHEAD);                      \
        float v0_ = a_.x + adv.x; v0_ = (v0_ < 0.f) ? v0_ * NEG : v0_;        \
        float v1_ = a_.y + adv.y; v1_ = (v1_ < 0.f) ? v1_ * NEG : v1_;        \
        float v2_ = a_.z + adv.z; v2_ = (v2_ < 0.f) ? v2_ * NEG : v2_;        \
        float v3_ = a_.w + adv.w; v3_ = (v3_ < 0.f) ? v3_ * NEG : v3_;        \
        float w0_ = __expf(v0_ - m0), w1_ = __expf(v1_ - m1);                 \
        float w2_ = __expf(v2_ - m2), w3_ = __expf(v3_ - m3);                 \
        ws0 += w0_; ws1 += w1_; ws2 += w2_; ws3 += w3_;                       \
        uint4 hv_ = ((const uint4*)(g_hwh + (size_t)s_ * HC))[lane];          \
        float w_ = (hsel == 0) ? w0_ : (hsel == 1) ? w1_ : (hsel == 2) ? w2_ : w3_; \
        float2 f0_ = __half22float2(*(const __half2*)&hv_.x);                 \
        float2 f1_ = __half22float2(*(const __half2*)&hv_.y);                 \
        float2 f2_ = __half22float2(*(const __half2*)&hv_.z);                 \
        float2 f3_ = __half22float2(*(const __half2*)&hv_.w);                 \
        acc[0] += w_ * f0_.x; acc[1] += w_ * f0_.y;                           \
        acc[2] += w_ * f1_.x; acc[3] += w_ * f1_.y;                           \
        acc[4] += w_ * f2_.x; acc[5] += w_ * f2_.y;                           \
        acc[6] += w_ * f3_.x; acc[7] += w_ * f3_.y;                           \
    }

    int p = r0;
    for (; p + 1 < r1; p += 2) { EDGE_STEP(p); EDGE_STEP(p + 1); }
    if (p < r1) EDGE_STEP(p);
#undef EDGE_STEP

    float i0 = 1.f / (ws0 + 1e-16f), i1 = 1.f / (ws1 + 1e-16f);
    float i2 = 1.f / (ws2 + 1e-16f), i3 = 1.f / (ws3 + 1e-16f);
    float wi = (hsel == 0) ? i0 : (hsel == 1) ? i1 : (hsel == 2) ? i2 : i3;

    float out[8];
#pragma unroll
    for (int qd = 0; qd < 8; qd++) {
        float s = acc[qd] * wi;
        s += __shfl_xor_sync(0xffffffffu, s, 8);
        s += __shfl_xor_sync(0xffffffffu, s, 16);
        out[qd] = s;
    }
    if (lane < 8) {
#pragma unroll
        for (int qd = 0; qd < 8; qd++) {
            float v = out[qd] * 0.25f + bg[lane * 8 + qd];
            out[qd] = (v > 0.f) ? v : 0.f;
        }
        float4* dst4 = (float4*)(g_h + (size_t)n * HIDD + lane * 8);
        dst4[0] = make_float4(out[0], out[1], out[2], out[3]);
        dst4[1] = make_float4(out[4], out[5], out[6], out[7]);
    }
}

__global__ void k_pool_init() {
    int i = blockIdx.x * blockDim.x + threadIdx.x;
    if (i < GG * HIDD) g_pool[i] = 0.f;
    if (i < GG) g_cnt[i] = 0.f;
}

// thread handles channel c over 8 consecutive (batch-sorted) nodes; run-length merge
__global__ void k_pool() {
    int i = blockIdx.x * blockDim.x + threadIdx.x;
    int c = i & 63;
    int n0 = (i >> 6) * 8;
    if (n0 >= NN) return;
    float run = 0.f; float cnt = 0.f; int gcur = -1;
#pragma unroll
    for (int t = 0; t < 8; t++) {
        int n = n0 + t;
        if (n >= NN) break;
        int g = g_batch[n];
        if (g != gcur) {
            if (gcur >= 0) {
                atomicAdd(&g_pool[gcur * HIDD + c], run);
                if (c == 0) atomicAdd(&g_cnt[gcur], cnt);
            }
            gcur = g; run = 0.f; cnt = 0.f;
        }
        run += g_h[n * HIDD + c];
        cnt += 1.f;
    }
    if (gcur >= 0) {
        atomicAdd(&g_pool[gcur * HIDD + c], run);
        if (c == 0) atomicAdd(&g_cnt[gcur], cnt);
    }
}

__global__ void k_final(const float* __restrict__ Wout, const float* __restrict__ bout,
                        float* __restrict__ out) {
    int g = threadIdx.x;
    if (g >= GG) return;
    float cnt = fmaxf(g_cnt[g], 1.f);
    float s = 0.f;
#pragma unroll
    for (int c = 0; c < HIDD; c++) s += (g_pool[g * HIDD + c] / cnt) * Wout[c];
    out[g] = 1.f / (1.f + expf(-(s + bout[0])));
}

// ---------------- launch ----------------
extern "C" void kernel_launch(void* const* d_in, const int* in_sizes, int n_in,
                              void* d_out, int out_size) {
    int ix, iei, ib, iwin, ibin, iwout, ibout, iw[3], ias[3], iad[3], ibg[3];
    if (n_in >= 2 && in_sizes[1] == 2 * EE) {
        ix = 0; iei = 1; ib = 2; iwin = 3; ibin = 4; iwout = 5; ibout = 6;
        for (int l = 0; l < 3; l++) { iw[l] = 7 + 4 * l; ias[l] = 8 + 4 * l; iad[l] = 9 + 4 * l; ibg[l] = 10 + 4 * l; }
    } else {
        ix = 0; iwin = 1; ibin = 2;
        for (int l = 0; l < 3; l++) { iw[l] = 3 + 4 * l; ias[l] = 4 + 4 * l; iad[l] = 5 + 4 * l; ibg[l] = 6 + 4 * l; }
        iwout = 15; ibout = 16; iei = 17; ib = 18;
    }

    const float* x     = (const float*)d_in[ix];
    const void*  ei    = d_in[iei];
    const void*  batch = d_in[ib];
    const float* W_in  = (const float*)d_in[iwin];
    const float* b_in  = (const float*)d_in[ibin];
    const float* W_out = (const float*)d_in[iwout];
    const float* b_out = (const float*)d_in[ibout];
    float* out = (float*)d_out;

    const int T = 256;
    auto gsz = [](long long n, int t) { return (int)((n + t - 1) / t); };

    // graph preprocessing (once per launch)
    k_detect<<<1, 1>>>(ei);
    k_zero_build<<<gsz(NN, T), T>>>();
    k_convert<<<gsz(ELNUM, T), T>>>(ei, batch);
    k_scan1<<<SCAN_NBLK, SCAN_B>>>();
    k_scan2<<<1, 32>>>();
    k_scan3<<<gsz(NN, T), T>>>();
    k_fill<<<gsz(ELNUM, T), T>>>();

    k_lin_in<<<gsz((long long)NN * HIDD, T), T>>>(x, W_in, b_in);

    for (int l = 0; l < 3; l++) {
        const float* W  = (const float*)d_in[iw[l]];
        const float* as = (const float*)d_in[ias[l]];
        const float* ad = (const float*)d_in[iad[l]];
        const float* bg = (const float*)d_in[ibg[l]];

        k_transpose<<<gsz(HIDD * HC, T), T>>>(W);
        k_hw_alpha<<<NN / MB, HC>>>(as, ad);
        k_attn_gather<<<gsz((long long)NN * 32, T), T>>>(bg);
    }

    k_pool_init<<<gsz((long long)GG * HIDD, T), T>>>();
    k_pool<<<gsz((long long)(NN / 8 + 1) * HIDD, T), T>>>();
    k_final<<<1, 64>>>(W_out, b_out, out);
}